// round 16
// baseline (speedup 1.0000x reference)
#include <cuda_runtime.h>
#include <cuda_fp16.h>
#include <cstdint>
#include <math.h>

#define SN       150000
#define DIM      512
#define NB       100
#define NUSE     104                 // computed n columns (13 tiles of 8)
#define NTILES   13
#define TALF     0.07f
#define S_PER_CTA 512
#define NCTA     ((SN + S_PER_CTA - 1) / S_PER_CTA)   // 293
#define POSBLK   25                  // 25 blocks x 4 n = 100 positive terms
#define TOTBLK   (NCTA + POSBLK)     // 318

// B words: 32 ksteps x (6 pairs x 128 + 32x2 tail) = 832/kstep = 26624 words
#define BW        (32 * NUSE * 8)                     // 26624 words = 104 KB
#define TAILW     24576                               // word offset of nt=12 region
#define SMEM_MAIN (BW * 4 + 16 * NUSE * 4)            // B + colacc[16][104]

// Static device scratch (no allocations allowed)
__device__ __align__(1024) unsigned g_B[BW];
__device__ float g_Psum[NCTA * 128];
__device__ float g_pos[128];
__device__ int   g_count;            // last-block counter (reset by prep each call)

// ---------------------------------------------------------------------------
__device__ __forceinline__ unsigned pack_f16x2(float lo, float hi) {
    unsigned r;  // first source -> high half
    asm("cvt.rn.f16x2.f32 %0, %1, %2;" : "=r"(r) : "f"(hi), "f"(lo));
    return r;
}
__device__ __forceinline__ void mma_f16acc(unsigned c[2], const unsigned* a,
                                           unsigned b0, unsigned b1) {
    asm volatile(
        "mma.sync.aligned.m16n8k16.row.col.f16.f16.f16.f16 "
        "{%0,%1},{%2,%3,%4,%5},{%6,%7},{%0,%1};\n"
        : "+r"(c[0]), "+r"(c[1])
        : "r"(a[0]), "r"(a[1]), "r"(a[2]), "r"(a[3]), "r"(b0), "r"(b1));
}
__device__ __forceinline__ void cp_async16(void* smem_dst, const void* gsrc) {
    unsigned s = (unsigned)__cvta_generic_to_shared(smem_dst);
    asm volatile("cp.async.cg.shared.global [%0], [%1], 16;\n" :: "r"(s), "l"(gsrc));
}

// ---------------------------------------------------------------------------
// prep: B'[n][k] = f16( fea[n][k] / (TAL*||fea[n]||) ), LDS.128-pair layout:
//   nt<12:  word[(kstep*6 + nt/2)*128 + (gid*4+tig)*4 + (nt&1)*2 + h]
//   nt==12: word[TAILW + (kstep*32 + gid*4+tig)*2 + h]
//   where n = nt*8+gid, k0 = kstep*16 + h*8 + tig*2 (value = pack(row[k0],k0+1))
// Block 0 also resets the last-block counter (runs before main every replay).
// ---------------------------------------------------------------------------
__global__ void prep_kernel(const float* __restrict__ fea) {
    int n = blockIdx.x;   // 0..103
    int t = threadIdx.x;  // 128
    if (n == 0 && t == 0) g_count = 0;
    __shared__ float red[128];
    __shared__ float row[512];
    float v[4]; float ss = 0.f;
    if (n < NB) {
#pragma unroll
        for (int i = 0; i < 4; i++) { v[i] = fea[n * DIM + t + i * 128]; ss += v[i] * v[i]; }
    } else { v[0] = v[1] = v[2] = v[3] = 0.f; }
    red[t] = ss; __syncthreads();
    for (int off = 64; off > 0; off >>= 1) { if (t < off) red[t] += red[t + off]; __syncthreads(); }
    float scale = (n < NB) ? (rsqrtf(red[0]) / TALF) : 0.f;
#pragma unroll
    for (int i = 0; i < 4; i++) row[t + i * 128] = v[i] * scale;
    __syncthreads();
    int nt  = n >> 3;
    int gid = n & 7;
#pragma unroll
    for (int i = 0; i < 2; i++) {
        int w = t + i * 128;        // enumerates (kstep, c) : 256 words per n
        int kstep = w >> 3;
        int c = w & 7;
        int tig = c >> 1, h = c & 1;
        int k0 = kstep * 16 + h * 8 + tig * 2;
        int lane = gid * 4 + tig;
        int idx;
        if (nt < 12) idx = (kstep * 6 + (nt >> 1)) * 128 + lane * 4 + (nt & 1) * 2 + h;
        else         idx = TAILW + (kstep * 32 + lane) * 2 + h;
        g_B[idx] = pack_f16x2(row[k0], row[k0 + 1]);
    }
}

// ---------------------------------------------------------------------------
// main: TOTBLK blocks x 512 threads.
//   blocks [0,293):   GEMM tile 512 s x 104 n, K=512.
//     m->s relabel: s(warp, m=8j+gid) = s_w + 4*gid + j, so each thread's A
//     needs per k-row are one float4 -> 4x LDG.128 per kstep (16 L1 wavefronts
//     instead of 64). Norms bit-identical (same 4-row accumulation order).
//   blocks [293,318): positive terms (4 n per block, exact fp32)
//   last block (atomic counter): logZ from Psum + final loss (fixed order).
// ---------------------------------------------------------------------------
#define LOADA(q, G)                                                         \
    do {                                                                    \
        const float* b_ = att + (size_t)((q) * 16 + 2 * tig) * SN_ + s0;    \
        (G)[0] = __ldcs((const float4*)(b_));                               \
        (G)[1] = __ldcs((const float4*)(b_ + SN_));                         \
        (G)[2] = __ldcs((const float4*)(b_ + 8 * SN_));                     \
        (G)[3] = __ldcs((const float4*)(b_ + 9 * SN_));                     \
    } while (0)

#define COMPUTE(q, G)                                                       \
    do {                                                                    \
        sq[0] += (G)[0].x*(G)[0].x + (G)[1].x*(G)[1].x                      \
               + (G)[2].x*(G)[2].x + (G)[3].x*(G)[3].x;                     \
        sq[1] += (G)[0].y*(G)[0].y + (G)[1].y*(G)[1].y                      \
               + (G)[2].y*(G)[2].y + (G)[3].y*(G)[3].y;                     \
        sq[2] += (G)[0].z*(G)[0].z + (G)[1].z*(G)[1].z                      \
               + (G)[2].z*(G)[2].z + (G)[3].z*(G)[3].z;                     \
        sq[3] += (G)[0].w*(G)[0].w + (G)[1].w*(G)[1].w                      \
               + (G)[2].w*(G)[2].w + (G)[3].w*(G)[3].w;                     \
        unsigned A_[2][4];                                                  \
        A_[0][0] = pack_f16x2((G)[0].x, (G)[1].x);                          \
        A_[0][1] = pack_f16x2((G)[0].y, (G)[1].y);                          \
        A_[0][2] = pack_f16x2((G)[2].x, (G)[3].x);                          \
        A_[0][3] = pack_f16x2((G)[2].y, (G)[3].y);                          \
        A_[1][0] = pack_f16x2((G)[0].z, (G)[1].z);                          \
        A_[1][1] = pack_f16x2((G)[0].w, (G)[1].w);                          \
        A_[1][2] = pack_f16x2((G)[2].z, (G)[3].z);                          \
        A_[1][3] = pack_f16x2((G)[2].w, (G)[3].w);                          \
        const uint4* bp_ = (const uint4*)Bsm + (q) * 6 * 32 + lane;         \
        _Pragma("unroll")                                                   \
        for (int p_ = 0; p_ < 6; p_++) {                                    \
            uint4 b_ = bp_[p_ * 32];                                        \
            mma_f16acc(acc[0][2*p_],     A_[0], b_.x, b_.y);                \
            mma_f16acc(acc[1][2*p_],     A_[1], b_.x, b_.y);                \
            mma_f16acc(acc[0][2*p_ + 1], A_[0], b_.z, b_.w);                \
            mma_f16acc(acc[1][2*p_ + 1], A_[1], b_.z, b_.w);                \
        }                                                                   \
        {                                                                   \
            uint2 b_ = ((const uint2*)(Bsm + TAILW))[(q) * 32 + lane];      \
            mma_f16acc(acc[0][12], A_[0], b_.x, b_.y);                      \
            mma_f16acc(acc[1][12], A_[1], b_.x, b_.y);                      \
        }                                                                   \
    } while (0)

__global__ void __launch_bounds__(512, 1)
main_kernel(const float* __restrict__ att, const float* __restrict__ fea,
            const int* __restrict__ label_raw, float* __restrict__ out) {
    extern __shared__ __align__(128) unsigned char smraw[];
    unsigned* Bsm    = (unsigned*)smraw;                     // BW words
    float*    colacc = (float*)(smraw + BW * 4);             // 16 x NUSE

    const int tid   = threadIdx.x;
    const int lane  = tid & 31;
    const int warp  = tid >> 5;
    const int gid   = lane >> 2;
    const int tig   = lane & 3;
    const int bid   = blockIdx.x;
    const size_t SN_ = (size_t)SN;

    if (bid < NCTA) {
        // ================= GEMM tile =================
        const int s_w = bid * S_PER_CTA + warp * 32;
        // component validity: acc row m=8j+gid <-> s = s_w + 4*gid + j
        bool pvc[4];
        int s0 = s_w + 4 * gid;
#pragma unroll
        for (int c = 0; c < 4; c++) pvc[c] = (s0 + c) < SN;
        if (s0 + 3 >= SN) s0 = SN - 4;   // clamp fully/partially-invalid lanes
        // note: k rows reach at most 511, s0 <= SN-4 -> all float4s in-bounds
        if (s0 + 3 >= SN) { /* unreachable; keeps compiler honest */ }
        // partially-valid lane (s0 clamped but some pvc true) cannot occur:
        // clamping only when s0+3>=SN; then original s0 >= SN-3; since s0 is
        // a multiple of 4 and SN%4==0, s0 >= SN -> all components invalid.

        unsigned acc[2][NTILES][2];
#pragma unroll
        for (int a = 0; a < 2; a++)
#pragma unroll
            for (int b = 0; b < NTILES; b++) { acc[a][b][0] = 0u; acc[a][b][1] = 0u; }
        float sq[4] = {0.f, 0.f, 0.f, 0.f};

        // one-shot B fill: 26624 words = 6656 x 16B, 13 per thread
#pragma unroll
        for (int i = 0; i < 13; i++) {
            int w = (tid + i * 512) * 4;
            cp_async16(&Bsm[w], &g_B[w]);
        }
        asm volatile("cp.async.commit_group;\n");

        float4 X0[4], X1[4];
        LOADA(0, X0);

        asm volatile("cp.async.wait_group 0;\n");
        __syncthreads();

#pragma unroll 2
        for (int q = 0; q < 32; q += 2) {
            if (q + 1 < 32) LOADA(q + 1, X1);
            COMPUTE(q, X0);
            if (q + 2 < 32) LOADA(q + 2, X0);
            COMPUTE(q + 1, X1);
        }

        // norm^2: quad-reduce over tig (lanes of a quad share the same 4 s)
#pragma unroll
        for (int j = 0; j < 4; j++) {
            sq[j] += __shfl_xor_sync(0xffffffffu, sq[j], 1);
            sq[j] += __shfl_xor_sync(0xffffffffu, sq[j], 2);
        }
        float inv[4];
#pragma unroll
        for (int j = 0; j < 4; j++) inv[j] = rsqrtf(sq[j]);

        // epilogue: unpack f16 accum, scale, exp, warp-level column sums
#pragma unroll
        for (int nt = 0; nt < NTILES; ++nt) {
            float e0 = 0.f, e1 = 0.f;
#pragma unroll
            for (int mf = 0; mf < 2; ++mf) {
                int j0 = 2 * mf, j1 = 2 * mf + 1;
                float2 v0 = __half22float2(*reinterpret_cast<__half2*>(&acc[mf][nt][0]));
                float2 v1 = __half22float2(*reinterpret_cast<__half2*>(&acc[mf][nt][1]));
                if (pvc[j0]) {
                    e0 += __expf(v0.x * inv[j0]);
                    e1 += __expf(v0.y * inv[j0]);
                }
                if (pvc[j1]) {
                    e0 += __expf(v1.x * inv[j1]);
                    e1 += __expf(v1.y * inv[j1]);
                }
            }
            e0 += __shfl_down_sync(0xffffffffu, e0, 16);
            e1 += __shfl_down_sync(0xffffffffu, e1, 16);
            e0 += __shfl_down_sync(0xffffffffu, e0, 8);
            e1 += __shfl_down_sync(0xffffffffu, e1, 8);
            e0 += __shfl_down_sync(0xffffffffu, e0, 4);
            e1 += __shfl_down_sync(0xffffffffu, e1, 4);
            if (gid == 0) {
                colacc[warp * NUSE + nt * 8 + 2 * tig]     = e0;
                colacc[warp * NUSE + nt * 8 + 2 * tig + 1] = e1;
            }
        }
        __syncthreads();

        if (tid < NUSE) {
            float s = 0.f;
#pragma unroll
            for (int g = 0; g < 16; ++g) s += colacc[g * NUSE + tid];
            g_Psum[bid * 128 + tid] = s;
        }
    } else {
        // ================= positive terms (4 n per block) =================
        int n = (bid - NCTA) * 4 + (tid >> 7);   // 0..99
        int t = tid & 127;
        float* r1 = (float*)smraw;               // 3 x 512 floats
        float* r2 = r1 + 512;
        float* r3 = r2 + 512;
        float dot = 0.f, asq = 0.f, fsq = 0.f;
        if (n < NB) {
            bool is64 = (label_raw[1] == 0) && (label_raw[3] == 0) &&
                        (label_raw[5] == 0) && (label_raw[7] == 0);
            int lab = is64 ? (int)(((const long long*)label_raw)[n]) : label_raw[n];
            if (lab < 0) lab = 0;
            if (lab >= SN) lab = SN - 1;
            for (int d = t; d < DIM; d += 128) {
                float a = att[(size_t)d * SN_ + (size_t)lab];
                float f = fea[n * DIM + d];
                dot += a * f; asq += a * a; fsq += f * f;
            }
        }
        r1[tid] = dot; r2[tid] = asq; r3[tid] = fsq; __syncthreads();
        for (int off = 64; off > 0; off >>= 1) {
            if (t < off) {
                r1[tid] += r1[tid + off];
                r2[tid] += r2[tid + off];
                r3[tid] += r3[tid + off];
            }
            __syncthreads();
        }
        if (t == 0 && n < NB)
            g_pos[n] = r1[tid] / (TALF * sqrtf(r2[tid]) * sqrtf(r3[tid]));
    }

    // ============ last-block-done: logZ + final loss ============
    __shared__ int islast;
    __syncthreads();
    if (tid == 0) {
        __threadfence();
        int prev = atomicAdd(&g_count, 1);
        islast = (prev == TOTBLK - 1) ? 1 : 0;
    }
    __syncthreads();
    if (islast) {
        __threadfence();
        float* red = (float*)smraw;   // 512 floats (Bsm dead by now)
        float v = 0.f;
        if (tid < NB) {
            float s = 0.f;
            for (int c = 0; c < NCTA; c++) s += g_Psum[c * 128 + tid];
            v = logf(s) - g_pos[tid];
        }
        red[tid] = v; __syncthreads();
        for (int off = 256; off > 0; off >>= 1) {
            if (tid < off) red[tid] += red[tid + off];
            __syncthreads();
        }
        if (tid == 0) out[0] = red[0] / (float)NB;
    }
}

// ---------------------------------------------------------------------------
extern "C" void kernel_launch(void* const* d_in, const int* in_sizes, int n_in,
                              void* d_out, int out_size) {
    int ia = 0, ifea = 1, ilab = 2;
    for (int i = 0; i < n_in; i++) {
        if (in_sizes[i] > 10000000) ia = i;
        else if (in_sizes[i] > 100000) ifea = i;
        else ilab = i;
    }
    const float* att   = (const float*)d_in[ia];
    const float* fea   = (const float*)d_in[ifea];
    const int*   label = (const int*)d_in[ilab];
    float* out = (float*)d_out;

    // Idempotent; safe under graph capture (no allocation, no sync).
    cudaFuncSetAttribute(main_kernel, cudaFuncAttributeMaxDynamicSharedMemorySize,
                         SMEM_MAIN);

    prep_kernel<<<NUSE, 128>>>(fea);
    main_kernel<<<TOTBLK, 512, SMEM_MAIN>>>(att, fea, label, out);
}

// round 17
// speedup vs baseline: 1.0336x; 1.0336x over previous
#include <cuda_runtime.h>
#include <cuda_fp16.h>
#include <cstdint>
#include <math.h>

#define SN       150000
#define DIM      512
#define NB       100
#define NUSE     104                 // computed n columns (13 tiles of 8)
#define NTILES   13
#define TALF     0.07f
#define S_PER_CTA 512
#define NCTA     ((SN + S_PER_CTA - 1) / S_PER_CTA)   // 293
#define POSBLK   25                  // 25 blocks x 4 n = 100 positive terms
#define TOTBLK   (NCTA + POSBLK)     // 318

// B words: 32 ksteps x (6 pairs x 128 + 32x2 tail) = 832/kstep = 26624 words
#define BW        (32 * NUSE * 8)                     // 26624 words = 104 KB
#define TAILW     24576                               // word offset of nt=12 region
#define SMEM_MAIN (BW * 4 + 16 * NUSE * 4)            // B + colacc[16][104]

// Static device scratch (no allocations allowed)
__device__ __align__(1024) unsigned g_B[BW];
__device__ float g_Psum[NCTA * 128];
__device__ float g_pos[128];
__device__ int   g_count;            // last-block counter (reset by prep each call)

// ---------------------------------------------------------------------------
__device__ __forceinline__ unsigned pack_f16x2(float lo, float hi) {
    unsigned r;  // first source -> high half
    asm("cvt.rn.f16x2.f32 %0, %1, %2;" : "=r"(r) : "f"(hi), "f"(lo));
    return r;
}
__device__ __forceinline__ void mma_f16acc(unsigned c[2], const unsigned* a,
                                           unsigned b0, unsigned b1) {
    asm volatile(
        "mma.sync.aligned.m16n8k16.row.col.f16.f16.f16.f16 "
        "{%0,%1},{%2,%3,%4,%5},{%6,%7},{%0,%1};\n"
        : "+r"(c[0]), "+r"(c[1])
        : "r"(a[0]), "r"(a[1]), "r"(a[2]), "r"(a[3]), "r"(b0), "r"(b1));
}
__device__ __forceinline__ void cp_async16(void* smem_dst, const void* gsrc) {
    unsigned s = (unsigned)__cvta_generic_to_shared(smem_dst);
    asm volatile("cp.async.cg.shared.global [%0], [%1], 16;\n" :: "r"(s), "l"(gsrc));
}

// ---------------------------------------------------------------------------
// prep: B'[n][k] = f16( fea[n][k] / (TAL*||fea[n]||) ), LDS.128-pair layout:
//   nt<12:  word[(kstep*6 + nt/2)*128 + (gid*4+tig)*4 + (nt&1)*2 + h]
//   nt==12: word[TAILW + (kstep*32 + gid*4+tig)*2 + h]
//   where n = nt*8+gid, k0 = kstep*16 + h*8 + tig*2 (value = pack(row[k0],k0+1))
// Block 0 also resets the last-block counter (runs before main every replay).
// ---------------------------------------------------------------------------
__global__ void prep_kernel(const float* __restrict__ fea) {
    int n = blockIdx.x;   // 0..103
    int t = threadIdx.x;  // 128
    if (n == 0 && t == 0) g_count = 0;
    __shared__ float red[128];
    __shared__ float row[512];
    float v[4]; float ss = 0.f;
    if (n < NB) {
#pragma unroll
        for (int i = 0; i < 4; i++) { v[i] = fea[n * DIM + t + i * 128]; ss += v[i] * v[i]; }
    } else { v[0] = v[1] = v[2] = v[3] = 0.f; }
    red[t] = ss; __syncthreads();
    for (int off = 64; off > 0; off >>= 1) { if (t < off) red[t] += red[t + off]; __syncthreads(); }
    float scale = (n < NB) ? (rsqrtf(red[0]) / TALF) : 0.f;
#pragma unroll
    for (int i = 0; i < 4; i++) row[t + i * 128] = v[i] * scale;
    __syncthreads();
    int nt  = n >> 3;
    int gid = n & 7;
#pragma unroll
    for (int i = 0; i < 2; i++) {
        int w = t + i * 128;        // enumerates (kstep, c) : 256 words per n
        int kstep = w >> 3;
        int c = w & 7;
        int tig = c >> 1, h = c & 1;
        int k0 = kstep * 16 + h * 8 + tig * 2;
        int lane = gid * 4 + tig;
        int idx;
        if (nt < 12) idx = (kstep * 6 + (nt >> 1)) * 128 + lane * 4 + (nt & 1) * 2 + h;
        else         idx = TAILW + (kstep * 32 + lane) * 2 + h;
        g_B[idx] = pack_f16x2(row[k0], row[k0 + 1]);
    }
}

// ---------------------------------------------------------------------------
// main: TOTBLK blocks x 512 threads (single launch after prep).
//   blocks [0,293):   GEMM tile 512 s x 104 n, K=512 (R8 loop, LDS.128 B)
//   blocks [293,318): positive terms (4 n per block, exact fp32)
//   last block (atomic counter): logZ from Psum + final loss, with the Psum
//   column sums split 4-way across the 512 threads (deterministic order).
// ---------------------------------------------------------------------------
#define LOADA(q, X)                                                         \
    do {                                                                    \
        const float* ap_ = att + (size_t)((q) * 16 + 2 * tig) * SN_;        \
        _Pragma("unroll")                                                   \
        for (int j_ = 0; j_ < 4; j_++) {                                    \
            if (pv[j_]) {                                                   \
                (X)[j_ * 4 + 0] = __ldcs(ap_ + srow[j_]);                   \
                (X)[j_ * 4 + 1] = __ldcs(ap_ + SN_ + srow[j_]);             \
                (X)[j_ * 4 + 2] = __ldcs(ap_ + 8 * SN_ + srow[j_]);         \
                (X)[j_ * 4 + 3] = __ldcs(ap_ + 9 * SN_ + srow[j_]);         \
            } else {                                                        \
                (X)[j_ * 4 + 0] = 0.f; (X)[j_ * 4 + 1] = 0.f;               \
                (X)[j_ * 4 + 2] = 0.f; (X)[j_ * 4 + 3] = 0.f;               \
            }                                                               \
        }                                                                   \
    } while (0)

#define COMPUTE(q, X)                                                       \
    do {                                                                    \
        _Pragma("unroll")                                                   \
        for (int j_ = 0; j_ < 4; j_++) {                                    \
            sq[j_] += (X)[j_*4+0]*(X)[j_*4+0] + (X)[j_*4+1]*(X)[j_*4+1]     \
                    + (X)[j_*4+2]*(X)[j_*4+2] + (X)[j_*4+3]*(X)[j_*4+3];    \
        }                                                                   \
        unsigned A_[2][4];                                                  \
        _Pragma("unroll")                                                   \
        for (int mf_ = 0; mf_ < 2; mf_++) {                                 \
            A_[mf_][0] = pack_f16x2((X)[(2*mf_)*4+0], (X)[(2*mf_)*4+1]);    \
            A_[mf_][1] = pack_f16x2((X)[(2*mf_+1)*4+0], (X)[(2*mf_+1)*4+1]);\
            A_[mf_][2] = pack_f16x2((X)[(2*mf_)*4+2], (X)[(2*mf_)*4+3]);    \
            A_[mf_][3] = pack_f16x2((X)[(2*mf_+1)*4+2], (X)[(2*mf_+1)*4+3]);\
        }                                                                   \
        const uint4* bp_ = (const uint4*)Bsm + (q) * 6 * 32 + lane;         \
        _Pragma("unroll")                                                   \
        for (int p_ = 0; p_ < 6; p_++) {                                    \
            uint4 b_ = bp_[p_ * 32];                                        \
            mma_f16acc(acc[0][2*p_],     A_[0], b_.x, b_.y);                \
            mma_f16acc(acc[1][2*p_],     A_[1], b_.x, b_.y);                \
            mma_f16acc(acc[0][2*p_ + 1], A_[0], b_.z, b_.w);                \
            mma_f16acc(acc[1][2*p_ + 1], A_[1], b_.z, b_.w);                \
        }                                                                   \
        {                                                                   \
            uint2 b_ = ((const uint2*)(Bsm + TAILW))[(q) * 32 + lane];      \
            mma_f16acc(acc[0][12], A_[0], b_.x, b_.y);                      \
            mma_f16acc(acc[1][12], A_[1], b_.x, b_.y);                      \
        }                                                                   \
    } while (0)

__global__ void __launch_bounds__(512, 1)
main_kernel(const float* __restrict__ att, const float* __restrict__ fea,
            const int* __restrict__ label_raw, float* __restrict__ out) {
    extern __shared__ __align__(128) unsigned char smraw[];
    unsigned* Bsm    = (unsigned*)smraw;                     // BW words
    float*    colacc = (float*)(smraw + BW * 4);             // 16 x NUSE

    const int tid   = threadIdx.x;
    const int lane  = tid & 31;
    const int warp  = tid >> 5;
    const int gid   = lane >> 2;
    const int tig   = lane & 3;
    const int bid   = blockIdx.x;
    const size_t SN_ = (size_t)SN;

    if (bid < NCTA) {
        // ================= GEMM tile =================
        const int s_w = bid * S_PER_CTA + warp * 32;
        int  srow[4];
        bool pv[4];
#pragma unroll
        for (int j = 0; j < 4; j++) {
            srow[j] = s_w + 8 * j + gid;
            pv[j]   = (srow[j] < SN);
        }

        unsigned acc[2][NTILES][2];
#pragma unroll
        for (int a = 0; a < 2; a++)
#pragma unroll
            for (int b = 0; b < NTILES; b++) { acc[a][b][0] = 0u; acc[a][b][1] = 0u; }
        float sq[4] = {0.f, 0.f, 0.f, 0.f};

        // one-shot B fill: 26624 words = 6656 x 16B, 13 per thread
#pragma unroll
        for (int i = 0; i < 13; i++) {
            int w = (tid + i * 512) * 4;
            cp_async16(&Bsm[w], &g_B[w]);
        }
        asm volatile("cp.async.commit_group;\n");

        float X0[16], X1[16];
        LOADA(0, X0);

        asm volatile("cp.async.wait_group 0;\n");
        __syncthreads();

#pragma unroll 2
        for (int q = 0; q < 32; q += 2) {
            if (q + 1 < 32) LOADA(q + 1, X1);
            COMPUTE(q, X0);
            if (q + 2 < 32) LOADA(q + 2, X0);
            COMPUTE(q + 1, X1);
        }

        // norm^2: quad-reduce over tig
#pragma unroll
        for (int j = 0; j < 4; j++) {
            sq[j] += __shfl_xor_sync(0xffffffffu, sq[j], 1);
            sq[j] += __shfl_xor_sync(0xffffffffu, sq[j], 2);
        }
        float inv[4];
#pragma unroll
        for (int j = 0; j < 4; j++) inv[j] = rsqrtf(sq[j]);

        // epilogue: unpack f16 accum, scale, exp, warp-level column sums
#pragma unroll
        for (int nt = 0; nt < NTILES; ++nt) {
            float e0 = 0.f, e1 = 0.f;
#pragma unroll
            for (int mf = 0; mf < 2; ++mf) {
                int j0 = 2 * mf, j1 = 2 * mf + 1;
                float2 v0 = __half22float2(*reinterpret_cast<__half2*>(&acc[mf][nt][0]));
                float2 v1 = __half22float2(*reinterpret_cast<__half2*>(&acc[mf][nt][1]));
                if (pv[j0]) {
                    e0 += __expf(v0.x * inv[j0]);
                    e1 += __expf(v0.y * inv[j0]);
                }
                if (pv[j1]) {
                    e0 += __expf(v1.x * inv[j1]);
                    e1 += __expf(v1.y * inv[j1]);
                }
            }
            e0 += __shfl_down_sync(0xffffffffu, e0, 16);
            e1 += __shfl_down_sync(0xffffffffu, e1, 16);
            e0 += __shfl_down_sync(0xffffffffu, e0, 8);
            e1 += __shfl_down_sync(0xffffffffu, e1, 8);
            e0 += __shfl_down_sync(0xffffffffu, e0, 4);
            e1 += __shfl_down_sync(0xffffffffu, e1, 4);
            if (gid == 0) {
                colacc[warp * NUSE + nt * 8 + 2 * tig]     = e0;
                colacc[warp * NUSE + nt * 8 + 2 * tig + 1] = e1;
            }
        }
        __syncthreads();

        if (tid < NUSE) {
            float s = 0.f;
#pragma unroll
            for (int g = 0; g < 16; ++g) s += colacc[g * NUSE + tid];
            g_Psum[bid * 128 + tid] = s;
        }
    } else {
        // ================= positive terms (4 n per block) =================
        int n = (bid - NCTA) * 4 + (tid >> 7);   // 0..99
        int t = tid & 127;
        float* r1 = (float*)smraw;               // 3 x 512 floats
        float* r2 = r1 + 512;
        float* r3 = r2 + 512;
        float dot = 0.f, asq = 0.f, fsq = 0.f;
        if (n < NB) {
            bool is64 = (label_raw[1] == 0) && (label_raw[3] == 0) &&
                        (label_raw[5] == 0) && (label_raw[7] == 0);
            int lab = is64 ? (int)(((const long long*)label_raw)[n]) : label_raw[n];
            if (lab < 0) lab = 0;
            if (lab >= SN) lab = SN - 1;
            for (int d = t; d < DIM; d += 128) {
                float a = att[(size_t)d * SN_ + (size_t)lab];
                float f = fea[n * DIM + d];
                dot += a * f; asq += a * a; fsq += f * f;
            }
        }
        r1[tid] = dot; r2[tid] = asq; r3[tid] = fsq; __syncthreads();
        for (int off = 64; off > 0; off >>= 1) {
            if (t < off) {
                r1[tid] += r1[tid + off];
                r2[tid] += r2[tid + off];
                r3[tid] += r3[tid + off];
            }
            __syncthreads();
        }
        if (t == 0 && n < NB)
            g_pos[n] = r1[tid] / (TALF * sqrtf(r2[tid]) * sqrtf(r3[tid]));
    }

    // ============ last-block-done: logZ + final loss ============
    __shared__ int islast;
    __syncthreads();
    if (tid == 0) {
        __threadfence();
        int prev = atomicAdd(&g_count, 1);
        islast = (prev == TOTBLK - 1) ? 1 : 0;
    }
    __syncthreads();
    if (islast) {
        __threadfence();
        float* red = (float*)smraw;   // 512 floats (Bsm dead by now)
        // Psum column sums, 4-way deterministic chunk split:
        // thread (ch, n) sums c = ch, ch+4, ... ; then fixed-order combine.
        {
            int n  = tid & 127;
            int ch = tid >> 7;        // 0..3
            float s = 0.f;
            for (int c = ch; c < NCTA; c += 4) s += g_Psum[c * 128 + n];
            red[tid] = s;
        }
        __syncthreads();
        float v = 0.f;
        if (tid < NB) {
            float z = ((red[tid] + red[128 + tid]) + red[256 + tid]) + red[384 + tid];
            v = logf(z) - g_pos[tid];
        }
        __syncthreads();
        red[tid] = v;   // v == 0 for tid >= NB
        __syncthreads();
        for (int off = 256; off > 0; off >>= 1) {
            if (tid < off) red[tid] += red[tid + off];
            __syncthreads();
        }
        if (tid == 0) out[0] = red[0] / (float)NB;
    }
}

// ---------------------------------------------------------------------------
extern "C" void kernel_launch(void* const* d_in, const int* in_sizes, int n_in,
                              void* d_out, int out_size) {
    int ia = 0, ifea = 1, ilab = 2;
    for (int i = 0; i < n_in; i++) {
        if (in_sizes[i] > 10000000) ia = i;
        else if (in_sizes[i] > 100000) ifea = i;
        else ilab = i;
    }
    const float* att   = (const float*)d_in[ia];
    const float* fea   = (const float*)d_in[ifea];
    const int*   label = (const int*)d_in[ilab];
    float* out = (float*)d_out;

    // Idempotent; safe under graph capture (no allocation, no sync).
    cudaFuncSetAttribute(main_kernel, cudaFuncAttributeMaxDynamicSharedMemorySize,
                         SMEM_MAIN);

    prep_kernel<<<NUSE, 128>>>(fea);
    main_kernel<<<TOTBLK, 512, SMEM_MAIN>>>(att, fea, label, out);
}